// round 13
// baseline (speedup 1.0000x reference)
#include <cuda_runtime.h>
#include <cuda_bf16.h>
#include <math.h>
#include <float.h>
#include <stdint.h>

// Problem constants
#define NTOT 65536          // B*H*W
#define CDIM 512            // channels / key dim
#define MDIM 512            // number of memory slots
#define HWDIM 4096          // H*W

// Output packing offsets (flat concat of the returned tuple, fp32)
#define OFF_UQ   0LL
#define OFF_UM   67108864LL           // 16*1024*4096
#define OFF_SQ   67371008LL           // + 512*512
#define OFF_SM   100925440LL          // + 65536*512
#define OFF_SEP  134479872LL          // + 65536*512
#define OFF_COMP 134479873LL

// ---------------- device scratch (no allocations allowed) ----------------
__device__ __nv_bfloat16  g_Eh[(size_t)NTOT * MDIM];     // E = exp(score), hi split
__device__ __nv_bfloat16  g_El[(size_t)NTOT * MDIM];     // E lo split
__device__ __nv_bfloat16  g_Ah[(size_t)NTOT * CDIM];     // qr hi split
__device__ __nv_bfloat16  g_Al[(size_t)NTOT * CDIM];     // qr lo split
__device__ __nv_bfloat16  g_Bh[(size_t)MDIM * CDIM];     // keys hi
__device__ __nv_bfloat16  g_Bl[(size_t)MDIM * CDIM];     // keys lo
__device__ __nv_bfloat16  g_BTh[(size_t)CDIM * MDIM];    // keysT hi
__device__ __nv_bfloat16  g_BTl[(size_t)CDIM * MDIM];    // keysT lo
__device__ float  g_rinv[NTOT];                   // 1 / rowsum(E)
__device__ float  g_cmax[MDIM];                   // column max of E
__device__ float  g_csum[MDIM];                   // column sum of E
__device__ float  g_w[NTOT];
__device__ int    g_gi[NTOT];
__device__ int    g_count[MDIM];
__device__ int    g_offset[MDIM + 1];
__device__ int    g_cursor[MDIM];
__device__ int    g_list[NTOT];
__device__ double g_comp, g_sep;

// ---------------- helpers ----------------
__device__ __forceinline__ void atomicMaxF(float* addr, float val) {
    int* ia = (int*)addr;
    int old = *ia;
    while (__int_as_float(old) < val) {
        int assumed = old;
        old = atomicCAS(ia, assumed, __float_as_int(val));
        if (old == assumed) break;
    }
}
__device__ __forceinline__ void bf16split(float v, __nv_bfloat16& h, __nv_bfloat16& l) {
    h = __float2bfloat16(v);
    l = __float2bfloat16(v - __bfloat162float(h));
}
__device__ __forceinline__ uint32_t packbf(__nv_bfloat16 a, __nv_bfloat16 b) {
    __nv_bfloat162 p; p.x = a; p.y = b;
    return *(uint32_t*)&p;
}

// ======================= bf16 3x-split warp-MMA GEMM =======================
// C[i, col0+j] = sum_k A[i,k] * B[col0+j, k]  with pre-split bf16 operands.
// CTA tile 64x128 (8 warps, warp tile 32x32), K-chunk 32, double-buffered
// smem (2 x 24KB), cp.async, 3 CTAs/SM.
// Stage layout (bytes): Ah 0..4K | Al 4K..8K | Bh 8K..16K | Bl 16K..24K
// Row = 64B (32 bf16), 4x16B chunks, chunk XOR-swizzled by (row>>1)&3.

__device__ __forceinline__ void ldm4(uint32_t* r, uint32_t a) {
    asm volatile("ldmatrix.sync.aligned.m8n8.x4.shared.b16 {%0,%1,%2,%3}, [%4];"
        : "=r"(r[0]), "=r"(r[1]), "=r"(r[2]), "=r"(r[3]) : "r"(a));
}
__device__ __forceinline__ void mma16816(float* d, const uint32_t* a, uint32_t b0, uint32_t b1) {
    asm volatile("mma.sync.aligned.m16n8k16.row.col.f32.bf16.bf16.f32 "
        "{%0,%1,%2,%3}, {%4,%5,%6,%7}, {%8,%9}, {%0,%1,%2,%3};"
        : "+f"(d[0]), "+f"(d[1]), "+f"(d[2]), "+f"(d[3])
        : "r"(a[0]), "r"(a[1]), "r"(a[2]), "r"(a[3]), "r"(b0), "r"(b1));
}
__device__ __forceinline__ void cpa16(uint32_t dst, const void* src) {
    asm volatile("cp.async.cg.shared.global [%0], [%1], 16;" :: "r"(dst), "l"(src));
}

__device__ __forceinline__ void stage_issue(const __nv_bfloat16* pAh, const __nv_bfloat16* pAl,
                                            const __nv_bfloat16* pBh, const __nv_bfloat16* pBl,
                                            uint32_t stb, uint32_t d0, int koff) {
    cpa16(stb + d0,                  pAh + koff);
    cpa16(stb + 4096u + d0,          pAl + koff);
    cpa16(stb + 8192u + d0,          pBh + koff);
    cpa16(stb + 8192u + d0 + 4096u,  pBh + koff + 32768);
    cpa16(stb + 16384u + d0,         pBl + koff);
    cpa16(stb + 16384u + d0 + 4096u, pBl + koff + 32768);
}

// EPI=0: e = exp(score); write bf16 hi/lo splits of e to g_Eh/g_El, accumulate
//        column max/sum of reconstructed e.
// EPI=1: scale rows by g_rinv, write transposed into output at (512+col) channels.
template <int EPI>
__global__ void __launch_bounds__(256, 3) k_mma(const __nv_bfloat16* __restrict__ Ah,
                                                const __nv_bfloat16* __restrict__ Al,
                                                const __nv_bfloat16* __restrict__ Bh,
                                                const __nv_bfloat16* __restrict__ Bl,
                                                float* __restrict__ Cout) {
    extern __shared__ char sm[];
    const int tid = threadIdx.x, lane = tid & 31, wid = tid >> 5;
    const size_t row0 = (size_t)blockIdx.y * 64;
    const int col0 = blockIdx.x * 128;
    const int warp_i = (wid & 1) * 32;      // 2 warps along i
    const int warp_j = (wid >> 1) * 32;     // 4 warps along j

    float acc[2][4][4];
    #pragma unroll
    for (int a = 0; a < 2; a++)
        #pragma unroll
        for (int b = 0; b < 4; b++)
            #pragma unroll
            for (int c = 0; c < 4; c++) acc[a][b][c] = 0.0f;

    const int lrow = (lane & 7) + ((lane >> 3) & 1) * 8;
    const int lsel = lane >> 4;
    const int arow = warp_i + lrow;
    const int asw  = (arow >> 1) & 3;
    const int brow = warp_j + lrow;
    const int bsw  = (brow >> 1) & 3;
    const uint32_t smb = (uint32_t)__cvta_generic_to_shared(sm);

    const int r0 = tid >> 2, cc4 = tid & 3;
    const uint32_t d0 = (uint32_t)(r0 * 64 + ((cc4 ^ ((r0 >> 1) & 3)) << 4));
    const __nv_bfloat16* pAh = Ah + (row0 + r0) * 512 + cc4 * 8;
    const __nv_bfloat16* pAl = Al + (row0 + r0) * 512 + cc4 * 8;
    const __nv_bfloat16* pBh = Bh + (size_t)(col0 + r0) * 512 + cc4 * 8;
    const __nv_bfloat16* pBl = Bl + (size_t)(col0 + r0) * 512 + cc4 * 8;

    stage_issue(pAh, pAl, pBh, pBl, smb, d0, 0);
    asm volatile("cp.async.commit_group;");

    #pragma unroll 2
    for (int ch = 0; ch < 16; ch++) {
        uint32_t stb = smb + (uint32_t)((ch & 1) ? 24576 : 0);
        if (ch < 15) {
            stage_issue(pAh, pAl, pBh, pBl, smb + (uint32_t)((ch & 1) ? 0 : 24576),
                        d0, (ch + 1) * 32);
            asm volatile("cp.async.commit_group;");
            asm volatile("cp.async.wait_group 1;");
        } else {
            asm volatile("cp.async.wait_group 0;");
        }
        __syncthreads();
        #pragma unroll
        for (int ks = 0; ks < 2; ks++) {
            int cidx = ks * 2 + lsel;
            uint32_t ah[2][4], al[2][4], bh[2][4], bl[2][4];
            #pragma unroll
            for (int fi = 0; fi < 2; fi++) {
                uint32_t ad = stb + (uint32_t)((arow + fi * 16) * 64 + ((cidx ^ asw) << 4));
                ldm4(ah[fi], ad);
                ldm4(al[fi], ad + 4096u);
            }
            #pragma unroll
            for (int g = 0; g < 2; g++) {
                uint32_t bd = stb + 8192u + (uint32_t)((brow + g * 16) * 64 + ((cidx ^ bsw) << 4));
                ldm4(bh[g], bd);
                ldm4(bl[g], bd + 8192u);
            }
            #pragma unroll
            for (int fi = 0; fi < 2; fi++)
                #pragma unroll
                for (int g = 0; g < 2; g++) {
                    mma16816(acc[fi][2*g],   ah[fi], bh[g][0], bh[g][2]);
                    mma16816(acc[fi][2*g+1], ah[fi], bh[g][1], bh[g][3]);
                }
            #pragma unroll
            for (int fi = 0; fi < 2; fi++)
                #pragma unroll
                for (int g = 0; g < 2; g++) {
                    mma16816(acc[fi][2*g],   al[fi], bh[g][0], bh[g][2]);
                    mma16816(acc[fi][2*g+1], al[fi], bh[g][1], bh[g][3]);
                }
            #pragma unroll
            for (int fi = 0; fi < 2; fi++)
                #pragma unroll
                for (int g = 0; g < 2; g++) {
                    mma16816(acc[fi][2*g],   ah[fi], bl[g][0], bl[g][2]);
                    mma16816(acc[fi][2*g+1], ah[fi], bl[g][1], bl[g][3]);
                }
        }
        __syncthreads();
    }

    if (EPI == 0) {
        // e = exp(score); write bf16 splits; col stats on reconstructed values
        float er[2][4][4];
        #pragma unroll
        for (int fi = 0; fi < 2; fi++) {
            size_t r = row0 + warp_i + fi * 16 + (lane >> 2);
            #pragma unroll
            for (int fj = 0; fj < 4; fj++) {
                int cw = col0 + warp_j + fj * 8 + (lane & 3) * 2;
                __nv_bfloat16 h0, l0, h1, l1, h2, l2, h3, l3;
                float e0 = __expf(acc[fi][fj][0]);
                float e1 = __expf(acc[fi][fj][1]);
                float e2 = __expf(acc[fi][fj][2]);
                float e3 = __expf(acc[fi][fj][3]);
                bf16split(e0, h0, l0); bf16split(e1, h1, l1);
                bf16split(e2, h2, l2); bf16split(e3, h3, l3);
                *(uint32_t*)&g_Eh[r * 512 + cw]       = packbf(h0, h1);
                *(uint32_t*)&g_El[r * 512 + cw]       = packbf(l0, l1);
                *(uint32_t*)&g_Eh[(r + 8) * 512 + cw] = packbf(h2, h3);
                *(uint32_t*)&g_El[(r + 8) * 512 + cw] = packbf(l2, l3);
                er[fi][fj][0] = __bfloat162float(h0) + __bfloat162float(l0);
                er[fi][fj][1] = __bfloat162float(h1) + __bfloat162float(l1);
                er[fi][fj][2] = __bfloat162float(h2) + __bfloat162float(l2);
                er[fi][fj][3] = __bfloat162float(h3) + __bfloat162float(l3);
            }
        }
        float* smax = (float*)sm;          // [128]
        float* ssum = smax + 128;          // [128]
        float lmax[4][2], lsum[4][2];
        #pragma unroll
        for (int fj = 0; fj < 4; fj++)
            #pragma unroll
            for (int p = 0; p < 2; p++) {
                float a0 = er[0][fj][p], a1 = er[0][fj][2 + p];
                float a2 = er[1][fj][p], a3 = er[1][fj][2 + p];
                lmax[fj][p] = fmaxf(fmaxf(a0, a1), fmaxf(a2, a3));
                lsum[fj][p] = a0 + a1 + a2 + a3;
            }
        #pragma unroll
        for (int off = 4; off < 32; off <<= 1)
            #pragma unroll
            for (int fj = 0; fj < 4; fj++)
                #pragma unroll
                for (int p = 0; p < 2; p++) {
                    lmax[fj][p] = fmaxf(lmax[fj][p], __shfl_xor_sync(0xffffffffu, lmax[fj][p], off));
                    lsum[fj][p] += __shfl_xor_sync(0xffffffffu, lsum[fj][p], off);
                }
        #pragma unroll
        for (int kk = 0; kk < 2; kk++) {
            if ((wid & 1) == kk && lane < 4) {
                #pragma unroll
                for (int fj = 0; fj < 4; fj++)
                    #pragma unroll
                    for (int p = 0; p < 2; p++) {
                        int c = warp_j + fj * 8 + lane * 2 + p;
                        if (kk == 0) { smax[c] = lmax[fj][p]; ssum[c] = lsum[fj][p]; }
                        else { smax[c] = fmaxf(smax[c], lmax[fj][p]); ssum[c] += lsum[fj][p]; }
                    }
            }
            __syncthreads();
        }
        if (tid < 128) {
            atomicMaxF(&g_cmax[col0 + tid], smax[tid]);
            atomicAdd(&g_csum[col0 + tid], ssum[tid]);
        }
    } else {
        // scale rows by 1/rowsum(E), then transposed write via smem tile
        #pragma unroll
        for (int fi = 0; fi < 2; fi++) {
            size_t rg = row0 + warp_i + fi * 16 + (lane >> 2);
            float ri0 = g_rinv[rg];
            float ri1 = g_rinv[rg + 8];
            #pragma unroll
            for (int fj = 0; fj < 4; fj++) {
                acc[fi][fj][0] *= ri0; acc[fi][fj][1] *= ri0;
                acc[fi][fj][2] *= ri1; acc[fi][fj][3] *= ri1;
            }
        }
        float* tile = (float*)sm;
        size_t b = row0 >> 12;
        int hw0 = (int)(row0 & 4095);
        float* obase = Cout + b * (1024LL * 4096LL) + (size_t)(512 + col0) * 4096;
        #pragma unroll
        for (int fi = 0; fi < 2; fi++) {
            int rr = warp_i + fi * 16 + (lane >> 2);
            #pragma unroll
            for (int fj = 0; fj < 4; fj++) {
                int cw = warp_j + fj * 8 + (lane & 3) * 2;
                tile[rr * 129 + cw]           = acc[fi][fj][0];
                tile[rr * 129 + cw + 1]       = acc[fi][fj][1];
                tile[(rr + 8) * 129 + cw]     = acc[fi][fj][2];
                tile[(rr + 8) * 129 + cw + 1] = acc[fi][fj][3];
            }
        }
        __syncthreads();
        #pragma unroll
        for (int it = 0; it < 16; it++) {
            int d = wid * 16 + it;
            float v0 = tile[lane * 129 + d];
            float v1 = tile[(lane + 32) * 129 + d];
            obase[(size_t)d * 4096 + hw0 + lane]      = v0;
            obase[(size_t)d * 4096 + hw0 + 32 + lane] = v1;
        }
    }
}

// ---------------- keys prep: splits of keys and keys^T ----------------
__global__ void k_prepkeys(const float* __restrict__ keys) {
    __shared__ float t[32][33];
    int c0 = blockIdx.x * 32;
    int r0 = blockIdx.y * 32;
    int tx = threadIdx.x, ty = threadIdx.y;
    for (int r = ty; r < 32; r += 8) {
        float v = keys[(size_t)(r0 + r) * 512 + c0 + tx];
        t[r][tx] = v;
        __nv_bfloat16 h, l; bf16split(v, h, l);
        g_Bh[(size_t)(r0 + r) * 512 + c0 + tx] = h;
        g_Bl[(size_t)(r0 + r) * 512 + c0 + tx] = l;
    }
    __syncthreads();
    for (int r = ty; r < 32; r += 8) {
        float v = t[tx][r];
        __nv_bfloat16 h, l; bf16split(v, h, l);
        g_BTh[(size_t)(c0 + r) * 512 + r0 + tx] = h;
        g_BTl[(size_t)(c0 + r) * 512 + r0 + tx] = l;
    }
}

// ---------------- init ----------------
__global__ void k_init() {
    int t = blockIdx.x * blockDim.x + threadIdx.x;
    if (t < MDIM) { g_cmax[t] = 0.0f; g_csum[t] = 0.0f; g_count[t] = 0; }
    if (t == 0) { g_comp = 0.0; g_sep = 0.0; }
}

// ---------------- L2 normalize + transpose to (N,C) + bf16 split + direct UQ output ----------------
__global__ void __launch_bounds__(256) k_normalize(const float* __restrict__ query,
                                                   float* __restrict__ out) {
    __shared__ float s[CDIM * 17];
    __shared__ float psum[256];
    __shared__ float rn[16];
    int p0 = blockIdx.x * 16;
    int b = p0 >> 12;
    int hw0 = p0 & 4095;
    const float* qb = query + (size_t)b * CDIM * HWDIM + hw0;
    int tid = threadIdx.x;
    #pragma unroll
    for (int it = 0; it < 32; it++) {
        int i = it * 256 + tid;
        int c = i >> 4, j = i & 15;
        s[c * 17 + j] = qb[(size_t)c * HWDIM + j];
    }
    __syncthreads();
    {
        int j = tid & 15, g = tid >> 4;
        float acc = 0.0f;
        #pragma unroll
        for (int cc = 0; cc < 32; cc++) {
            float v = s[(g * 32 + cc) * 17 + j];
            acc += v * v;
        }
        psum[tid] = acc;
    }
    __syncthreads();
    if (tid < 16) {
        float tot = 0.0f;
        #pragma unroll
        for (int g = 0; g < 16; g++) tot += psum[g * 16 + tid];
        rn[tid] = 1.0f / fmaxf(sqrtf(tot), 1e-12f);
    }
    __syncthreads();
    #pragma unroll
    for (int it = 0; it < 32; it++) {
        int i = it * 256 + tid;
        int c = i & 511, j = i >> 9;
        float v = s[c * 17 + j] * rn[j];
        size_t idx = (size_t)(p0 + j) * CDIM + c;
        __nv_bfloat16 h, l; bf16split(v, h, l);
        g_Ah[idx] = h;
        g_Al[idx] = l;
    }
    float* ob = out + (size_t)b * (1024LL * 4096LL) + hw0;
    #pragma unroll
    for (int it = 0; it < 32; it++) {
        int i = it * 256 + tid;
        int c = i >> 4, j = i & 15;
        ob[(size_t)c * 4096 + j] = s[c * 17 + j] * rn[j];
    }
}

// ---------------- per-row pass on E-splits: softmaxes, top2, w, losses ----------------
__global__ void __launch_bounds__(256) k_row(float* __restrict__ out_sq,
                                             float* __restrict__ out_sm,
                                             const float* __restrict__ keys) {
    __shared__ float cinv[512];
    __shared__ double wcomp[8], wsep[8];
    for (int i = threadIdx.x; i < 512; i += 256)
        cinv[i] = 1.0f / g_csum[i];
    __syncthreads();
    int warp = threadIdx.x >> 5, lane = threadIdx.x & 31;
    size_t n = (size_t)blockIdx.x * 8 + warp;
    const __nv_bfloat16* ehrow = g_Eh + n * 512;
    const __nv_bfloat16* elrow = g_El + n * 512;
    float ev[16];
    #pragma unroll
    for (int t = 0; t < 16; t++) {
        int c = lane + t * 32;
        ev[t] = __bfloat162float(ehrow[c]) + __bfloat162float(elrow[c]);
    }

    // top2 on E (monotone in score)
    float v1 = -FLT_MAX, v2 = -FLT_MAX; int i1 = 0, i2 = 0;
    #pragma unroll
    for (int t = 0; t < 16; t++) {
        int c = lane + t * 32; float v = ev[t];
        if (v > v1) { v2 = v1; i2 = i1; v1 = v; i1 = c; }
        else if (v > v2) { v2 = v; i2 = c; }
    }
    #pragma unroll
    for (int off = 16; off; off >>= 1) {
        float ov1 = __shfl_down_sync(0xffffffffu, v1, off);
        int   oi1 = __shfl_down_sync(0xffffffffu, i1, off);
        float ov2 = __shfl_down_sync(0xffffffffu, v2, off);
        int   oi2 = __shfl_down_sync(0xffffffffu, i2, off);
        if (ov1 > v1) { v2 = v1; i2 = i1; v1 = ov1; i1 = oi1; if (ov2 > v2) { v2 = ov2; i2 = oi2; } }
        else if (ov1 > v2) { v2 = ov1; i2 = oi1; }
    }
    v1 = __shfl_sync(0xffffffffu, v1, 0);
    i1 = __shfl_sync(0xffffffffu, i1, 0);
    i2 = __shfl_sync(0xffffffffu, i2, 0);

    // row sum of E
    float rs = 0.0f;
    #pragma unroll
    for (int t = 0; t < 16; t++) rs += ev[t];
    #pragma unroll
    for (int o = 16; o; o >>= 1) rs += __shfl_xor_sync(0xffffffffu, rs, o);
    float inv_rs = 1.0f / rs;
    float* smrow = out_sm + n * 512;
    float* sqrow = out_sq + n * 512;
    #pragma unroll
    for (int t = 0; t < 16; t++) {
        int c = lane + t * 32;
        smrow[c] = ev[t] * inv_rs;
        sqrow[c] = ev[t] * cinv[c];
    }
    if (lane == 0) {
        g_gi[n] = i1;
        g_w[n] = v1 / g_cmax[i1];
        g_rinv[n] = inv_rs;
        atomicAdd(&g_count[i1], 1);
    }

    const __nv_bfloat16* qh = g_Ah + n * 512;
    const __nv_bfloat16* ql = g_Al + n * 512;
    const float* pk = keys + (size_t)i1 * 512;
    const float* nk = keys + (size_t)i2 * 512;
    float comp = 0.0f, dp = 0.0f, dn = 0.0f;
    #pragma unroll
    for (int t = 0; t < 16; t++) {
        int c = lane + t * 32;
        float q = __bfloat162float(qh[c]) + __bfloat162float(ql[c]);
        float p = pk[c], gg = nk[c];
        float d0 = q - p; comp += d0 * d0;
        float d1 = d0 + 1e-6f; dp += d1 * d1;
        float d2 = (q - gg) + 1e-6f; dn += d2 * d2;
    }
    #pragma unroll
    for (int o = 16; o; o >>= 1) {
        comp += __shfl_xor_sync(0xffffffffu, comp, o);
        dp   += __shfl_xor_sync(0xffffffffu, dp, o);
        dn   += __shfl_xor_sync(0xffffffffu, dn, o);
    }
    if (lane == 0) {
        wcomp[warp] = (double)comp;
        wsep[warp] = (double)fmaxf(0.0f, sqrtf(dp) - sqrtf(dn) + 1.0f);
    }
    __syncthreads();
    if (threadIdx.x == 0) {
        double c = 0.0, s = 0.0;
        for (int wv = 0; wv < 8; wv++) { c += wcomp[wv]; s += wsep[wv]; }
        atomicAdd(&g_comp, c);
        atomicAdd(&g_sep, s);
    }
}

// ---------------- counting sort of rows by gi ----------------
__global__ void __launch_bounds__(512) k_scan() {
    __shared__ int s[512];
    int t = threadIdx.x;
    int v = g_count[t];
    s[t] = v;
    __syncthreads();
    for (int off = 1; off < 512; off <<= 1) {
        int add = (t >= off) ? s[t - off] : 0;
        __syncthreads();
        s[t] += add;
        __syncthreads();
    }
    g_offset[t + 1] = s[t];
    if (t == 0) g_offset[0] = 0;
    g_cursor[t] = s[t] - v;
}

__global__ void k_scatter() {
    for (int n = blockIdx.x * blockDim.x + threadIdx.x; n < NTOT; n += gridDim.x * blockDim.x) {
        int m = g_gi[n];
        int idx = atomicAdd(&g_cursor[m], 1);
        g_list[idx] = n;
    }
}

// ---------------- memory update: segment sum + l2norm ----------------
__global__ void __launch_bounds__(512) k_update(const float* __restrict__ keys,
                                                float* __restrict__ outUM) {
    int m = blockIdx.x;
    int t = threadIdx.x;
    __shared__ int sln[256];
    __shared__ float slw[256];
    __shared__ float red[16];
    __shared__ float rn_s;
    int beg = g_offset[m], end = g_offset[m + 1];
    float acc = 0.0f;
    for (int base = beg; base < end; base += 256) {
        int cnt = min(256, end - base);
        __syncthreads();
        if (t < cnt) { int n = g_list[base + t]; sln[t] = n; slw[t] = g_w[n]; }
        __syncthreads();
        for (int i = 0; i < cnt; i++) {
            size_t idx = (size_t)sln[i] * 512 + t;
            float q = __bfloat162float(g_Ah[idx]) + __bfloat162float(g_Al[idx]);
            acc += slw[i] * q;
        }
    }
    float um = acc + keys[(size_t)m * 512 + t];
    float ss = um * um;
    #pragma unroll
    for (int o = 16; o; o >>= 1) ss += __shfl_xor_sync(0xffffffffu, ss, o);
    if ((t & 31) == 0) red[t >> 5] = ss;
    __syncthreads();
    if (t == 0) {
        float x = 0.0f;
        for (int i = 0; i < 16; i++) x += red[i];
        rn_s = 1.0f / fmaxf(sqrtf(x), 1e-12f);
    }
    __syncthreads();
    outUM[(size_t)m * 512 + t] = um * rn_s;
}

// ---------------- losses ----------------
__global__ void k_finalize(float* __restrict__ out) {
    out[OFF_SEP] = (float)(g_sep / (double)NTOT);
    out[OFF_COMP] = (float)(g_comp / ((double)NTOT * (double)CDIM));
}

// ---------------- launch ----------------
extern "C" void kernel_launch(void* const* d_in, const int* in_sizes, int n_in,
                              void* d_out, int out_size) {
    const float* query = (const float*)d_in[0];
    const float* keys  = (const float*)d_in[1];
    float* out = (float*)d_out;

    __nv_bfloat16 *p_Eh = nullptr, *p_El = nullptr, *p_Ah = nullptr, *p_Al = nullptr;
    __nv_bfloat16 *p_Bh = nullptr, *p_Bl = nullptr, *p_BTh = nullptr, *p_BTl = nullptr;
    cudaGetSymbolAddress((void**)&p_Eh, g_Eh);
    cudaGetSymbolAddress((void**)&p_El, g_El);
    cudaGetSymbolAddress((void**)&p_Ah, g_Ah);
    cudaGetSymbolAddress((void**)&p_Al, g_Al);
    cudaGetSymbolAddress((void**)&p_Bh, g_Bh);
    cudaGetSymbolAddress((void**)&p_Bl, g_Bl);
    cudaGetSymbolAddress((void**)&p_BTh, g_BTh);
    cudaGetSymbolAddress((void**)&p_BTl, g_BTl);

    cudaFuncSetAttribute(k_mma<0>, cudaFuncAttributeMaxDynamicSharedMemorySize, 49152);
    cudaFuncSetAttribute(k_mma<1>, cudaFuncAttributeMaxDynamicSharedMemorySize, 49152);

    k_init<<<2, 256>>>();
    k_normalize<<<NTOT / 16, 256>>>(query, out);
    k_prepkeys<<<dim3(16, 16), dim3(32, 8)>>>(keys);
    k_mma<0><<<dim3(4, NTOT / 64), 256, 49152>>>(p_Ah, p_Al, p_Bh, p_Bl, out);
    k_row<<<NTOT / 8, 256>>>(out + OFF_SQ, out + OFF_SM, keys);
    k_scan<<<1, 512>>>();
    k_scatter<<<64, 256>>>();
    k_update<<<MDIM, 512>>>(keys, out + OFF_UM);
    k_mma<1><<<dim3(4, NTOT / 64), 256, 49152>>>(p_Eh, p_El, p_BTh, p_BTl, out);
    k_finalize<<<1, 1>>>(out);
}

// round 14
// speedup vs baseline: 1.0352x; 1.0352x over previous
#include <cuda_runtime.h>
#include <cuda_bf16.h>
#include <math.h>
#include <float.h>
#include <stdint.h>

// Problem constants
#define NTOT 65536          // B*H*W
#define CDIM 512            // channels / key dim
#define MDIM 512            // number of memory slots
#define HWDIM 4096          // H*W

// Output packing offsets (flat concat of the returned tuple, fp32)
#define OFF_UQ   0LL
#define OFF_UM   67108864LL           // 16*1024*4096
#define OFF_SQ   67371008LL           // + 512*512
#define OFF_SM   100925440LL          // + 65536*512
#define OFF_SEP  134479872LL          // + 65536*512
#define OFF_COMP 134479873LL

// ---------------- device scratch (no allocations allowed) ----------------
__device__ float          g_E[(size_t)NTOT * MDIM];      // E = exp(score)
__device__ __nv_bfloat16  g_Ah[(size_t)NTOT * CDIM];     // qr hi split
__device__ __nv_bfloat16  g_Al[(size_t)NTOT * CDIM];     // qr lo split
__device__ __nv_bfloat16  g_Sh[(size_t)NTOT * CDIM];     // s_memory hi split
__device__ __nv_bfloat16  g_Sl[(size_t)NTOT * CDIM];     // s_memory lo split
__device__ __nv_bfloat16  g_Bh[(size_t)MDIM * CDIM];     // keys hi
__device__ __nv_bfloat16  g_Bl[(size_t)MDIM * CDIM];     // keys lo
__device__ __nv_bfloat16  g_BTh[(size_t)CDIM * MDIM];    // keysT hi
__device__ __nv_bfloat16  g_BTl[(size_t)CDIM * MDIM];    // keysT lo
__device__ float  g_cmax[MDIM];                   // column max of E
__device__ float  g_csum[MDIM];                   // column sum of E
__device__ float  g_w[NTOT];
__device__ int    g_gi[NTOT];
__device__ int    g_count[MDIM];
__device__ int    g_offset[MDIM + 1];
__device__ int    g_cursor[MDIM];
__device__ int    g_list[NTOT];
__device__ double g_comp, g_sep;

// ---------------- helpers ----------------
__device__ __forceinline__ void atomicMaxF(float* addr, float val) {
    int* ia = (int*)addr;
    int old = *ia;
    while (__int_as_float(old) < val) {
        int assumed = old;
        old = atomicCAS(ia, assumed, __float_as_int(val));
        if (old == assumed) break;
    }
}
__device__ __forceinline__ void bf16split(float v, __nv_bfloat16& h, __nv_bfloat16& l) {
    h = __float2bfloat16(v);
    l = __float2bfloat16(v - __bfloat162float(h));
}
__device__ __forceinline__ uint32_t packbf(__nv_bfloat16 a, __nv_bfloat16 b) {
    __nv_bfloat162 p; p.x = a; p.y = b;
    return *(uint32_t*)&p;
}

// ======================= bf16 3x-split warp-MMA GEMM =======================
// C[i, col0+j] = sum_k A[i,k] * B[col0+j, k]  with pre-split bf16 operands.
// CTA tile 64x128 (8 warps, warp tile 32x32), K-chunk 32, double-buffered
// smem (2 x 24KB), cp.async, 3 CTAs/SM.
// Stage layout (bytes): Ah 0..4K | Al 4K..8K | Bh 8K..16K | Bl 16K..24K
// Row = 64B (32 bf16), 4x16B chunks, chunk XOR-swizzled by (row>>1)&3.

__device__ __forceinline__ void ldm4(uint32_t* r, uint32_t a) {
    asm volatile("ldmatrix.sync.aligned.m8n8.x4.shared.b16 {%0,%1,%2,%3}, [%4];"
        : "=r"(r[0]), "=r"(r[1]), "=r"(r[2]), "=r"(r[3]) : "r"(a));
}
__device__ __forceinline__ void mma16816(float* d, const uint32_t* a, uint32_t b0, uint32_t b1) {
    asm volatile("mma.sync.aligned.m16n8k16.row.col.f32.bf16.bf16.f32 "
        "{%0,%1,%2,%3}, {%4,%5,%6,%7}, {%8,%9}, {%0,%1,%2,%3};"
        : "+f"(d[0]), "+f"(d[1]), "+f"(d[2]), "+f"(d[3])
        : "r"(a[0]), "r"(a[1]), "r"(a[2]), "r"(a[3]), "r"(b0), "r"(b1));
}
__device__ __forceinline__ void cpa16(uint32_t dst, const void* src) {
    asm volatile("cp.async.cg.shared.global [%0], [%1], 16;" :: "r"(dst), "l"(src));
}

__device__ __forceinline__ void stage_issue(const __nv_bfloat16* pAh, const __nv_bfloat16* pAl,
                                            const __nv_bfloat16* pBh, const __nv_bfloat16* pBl,
                                            uint32_t stb, uint32_t d0, int koff) {
    cpa16(stb + d0,                  pAh + koff);
    cpa16(stb + 4096u + d0,          pAl + koff);
    cpa16(stb + 8192u + d0,          pBh + koff);
    cpa16(stb + 8192u + d0 + 4096u,  pBh + koff + 32768);
    cpa16(stb + 16384u + d0,         pBl + koff);
    cpa16(stb + 16384u + d0 + 4096u, pBl + koff + 32768);
}

// EPI=0: write E = exp(score) row-major (N x 512) AND accumulate col max/sum of E.
// EPI=1: write transposed into output: Cout[b*1024*4096 + (512+col0+d)*4096 + hw]
template <int EPI>
__global__ void __launch_bounds__(256, 3) k_mma(const __nv_bfloat16* __restrict__ Ah,
                                                const __nv_bfloat16* __restrict__ Al,
                                                const __nv_bfloat16* __restrict__ Bh,
                                                const __nv_bfloat16* __restrict__ Bl,
                                                float* __restrict__ Cout) {
    extern __shared__ char sm[];
    const int tid = threadIdx.x, lane = tid & 31, wid = tid >> 5;
    const size_t row0 = (size_t)blockIdx.y * 64;
    const int col0 = blockIdx.x * 128;
    const int warp_i = (wid & 1) * 32;      // 2 warps along i
    const int warp_j = (wid >> 1) * 32;     // 4 warps along j

    float acc[2][4][4];
    #pragma unroll
    for (int a = 0; a < 2; a++)
        #pragma unroll
        for (int b = 0; b < 4; b++)
            #pragma unroll
            for (int c = 0; c < 4; c++) acc[a][b][c] = 0.0f;

    const int lrow = (lane & 7) + ((lane >> 3) & 1) * 8;
    const int lsel = lane >> 4;
    const int arow = warp_i + lrow;
    const int asw  = (arow >> 1) & 3;
    const int brow = warp_j + lrow;
    const int bsw  = (brow >> 1) & 3;
    const uint32_t smb = (uint32_t)__cvta_generic_to_shared(sm);

    const int r0 = tid >> 2, cc4 = tid & 3;
    const uint32_t d0 = (uint32_t)(r0 * 64 + ((cc4 ^ ((r0 >> 1) & 3)) << 4));
    const __nv_bfloat16* pAh = Ah + (row0 + r0) * 512 + cc4 * 8;
    const __nv_bfloat16* pAl = Al + (row0 + r0) * 512 + cc4 * 8;
    const __nv_bfloat16* pBh = Bh + (size_t)(col0 + r0) * 512 + cc4 * 8;
    const __nv_bfloat16* pBl = Bl + (size_t)(col0 + r0) * 512 + cc4 * 8;

    stage_issue(pAh, pAl, pBh, pBl, smb, d0, 0);
    asm volatile("cp.async.commit_group;");

    #pragma unroll 2
    for (int ch = 0; ch < 16; ch++) {
        uint32_t stb = smb + (uint32_t)((ch & 1) ? 24576 : 0);
        if (ch < 15) {
            stage_issue(pAh, pAl, pBh, pBl, smb + (uint32_t)((ch & 1) ? 0 : 24576),
                        d0, (ch + 1) * 32);
            asm volatile("cp.async.commit_group;");
            asm volatile("cp.async.wait_group 1;");
        } else {
            asm volatile("cp.async.wait_group 0;");
        }
        __syncthreads();
        #pragma unroll
        for (int ks = 0; ks < 2; ks++) {
            int cidx = ks * 2 + lsel;
            uint32_t ah[2][4], al[2][4], bh[2][4], bl[2][4];
            #pragma unroll
            for (int fi = 0; fi < 2; fi++) {
                uint32_t ad = stb + (uint32_t)((arow + fi * 16) * 64 + ((cidx ^ asw) << 4));
                ldm4(ah[fi], ad);
                ldm4(al[fi], ad + 4096u);
            }
            #pragma unroll
            for (int g = 0; g < 2; g++) {
                uint32_t bd = stb + 8192u + (uint32_t)((brow + g * 16) * 64 + ((cidx ^ bsw) << 4));
                ldm4(bh[g], bd);
                ldm4(bl[g], bd + 8192u);
            }
            #pragma unroll
            for (int fi = 0; fi < 2; fi++)
                #pragma unroll
                for (int g = 0; g < 2; g++) {
                    mma16816(acc[fi][2*g],   ah[fi], bh[g][0], bh[g][2]);
                    mma16816(acc[fi][2*g+1], ah[fi], bh[g][1], bh[g][3]);
                }
            #pragma unroll
            for (int fi = 0; fi < 2; fi++)
                #pragma unroll
                for (int g = 0; g < 2; g++) {
                    mma16816(acc[fi][2*g],   al[fi], bh[g][0], bh[g][2]);
                    mma16816(acc[fi][2*g+1], al[fi], bh[g][1], bh[g][3]);
                }
            #pragma unroll
            for (int fi = 0; fi < 2; fi++)
                #pragma unroll
                for (int g = 0; g < 2; g++) {
                    mma16816(acc[fi][2*g],   ah[fi], bl[g][0], bl[g][2]);
                    mma16816(acc[fi][2*g+1], ah[fi], bl[g][1], bl[g][3]);
                }
        }
        __syncthreads();
    }

    if (EPI == 0) {
        // E = exp(score): compute once, write E, derive col stats from E
        float e[2][4][4];
        #pragma unroll
        for (int fi = 0; fi < 2; fi++)
            #pragma unroll
            for (int fj = 0; fj < 4; fj++)
                #pragma unroll
                for (int p = 0; p < 4; p++)
                    e[fi][fj][p] = __expf(acc[fi][fj][p]);
        #pragma unroll
        for (int fi = 0; fi < 2; fi++) {
            size_t r = row0 + warp_i + fi * 16 + (lane >> 2);
            #pragma unroll
            for (int fj = 0; fj < 4; fj++) {
                int cw = col0 + warp_j + fj * 8 + (lane & 3) * 2;
                *(float2*)&Cout[r * 512 + cw]       = make_float2(e[fi][fj][0], e[fi][fj][1]);
                *(float2*)&Cout[(r + 8) * 512 + cw] = make_float2(e[fi][fj][2], e[fi][fj][3]);
            }
        }
        float* smax = (float*)sm;          // [128]
        float* ssum = smax + 128;          // [128]
        float lmax[4][2], lsum[4][2];
        #pragma unroll
        for (int fj = 0; fj < 4; fj++)
            #pragma unroll
            for (int p = 0; p < 2; p++) {
                float a0 = e[0][fj][p], a1 = e[0][fj][2 + p];
                float a2 = e[1][fj][p], a3 = e[1][fj][2 + p];
                lmax[fj][p] = fmaxf(fmaxf(a0, a1), fmaxf(a2, a3));
                lsum[fj][p] = a0 + a1 + a2 + a3;
            }
        #pragma unroll
        for (int off = 4; off < 32; off <<= 1)
            #pragma unroll
            for (int fj = 0; fj < 4; fj++)
                #pragma unroll
                for (int p = 0; p < 2; p++) {
                    lmax[fj][p] = fmaxf(lmax[fj][p], __shfl_xor_sync(0xffffffffu, lmax[fj][p], off));
                    lsum[fj][p] += __shfl_xor_sync(0xffffffffu, lsum[fj][p], off);
                }
        #pragma unroll
        for (int kk = 0; kk < 2; kk++) {
            if ((wid & 1) == kk && lane < 4) {
                #pragma unroll
                for (int fj = 0; fj < 4; fj++)
                    #pragma unroll
                    for (int p = 0; p < 2; p++) {
                        int c = warp_j + fj * 8 + lane * 2 + p;
                        if (kk == 0) { smax[c] = lmax[fj][p]; ssum[c] = lsum[fj][p]; }
                        else { smax[c] = fmaxf(smax[c], lmax[fj][p]); ssum[c] += lsum[fj][p]; }
                    }
            }
            __syncthreads();
        }
        if (tid < 128) {
            atomicMaxF(&g_cmax[col0 + tid], smax[tid]);
            atomicAdd(&g_csum[col0 + tid], ssum[tid]);
        }
    } else {
        // transposed write via smem tile 64 x 128 fp32, stride 129 (conflict-free)
        float* tile = (float*)sm;
        size_t b = row0 >> 12;
        int hw0 = (int)(row0 & 4095);
        float* obase = Cout + b * (1024LL * 4096LL) + (size_t)(512 + col0) * 4096;
        #pragma unroll
        for (int fi = 0; fi < 2; fi++) {
            int rr = warp_i + fi * 16 + (lane >> 2);
            #pragma unroll
            for (int fj = 0; fj < 4; fj++) {
                int cw = warp_j + fj * 8 + (lane & 3) * 2;
                tile[rr * 129 + cw]           = acc[fi][fj][0];
                tile[rr * 129 + cw + 1]       = acc[fi][fj][1];
                tile[(rr + 8) * 129 + cw]     = acc[fi][fj][2];
                tile[(rr + 8) * 129 + cw + 1] = acc[fi][fj][3];
            }
        }
        __syncthreads();
        #pragma unroll
        for (int it = 0; it < 16; it++) {
            int d = wid * 16 + it;
            float v0 = tile[lane * 129 + d];
            float v1 = tile[(lane + 32) * 129 + d];
            obase[(size_t)d * 4096 + hw0 + lane]      = v0;
            obase[(size_t)d * 4096 + hw0 + 32 + lane] = v1;
        }
    }
}

// ---------------- keys prep: splits of keys and keys^T ----------------
__global__ void k_prepkeys(const float* __restrict__ keys) {
    __shared__ float t[32][33];
    int c0 = blockIdx.x * 32;
    int r0 = blockIdx.y * 32;
    int tx = threadIdx.x, ty = threadIdx.y;
    for (int r = ty; r < 32; r += 8) {
        float v = keys[(size_t)(r0 + r) * 512 + c0 + tx];
        t[r][tx] = v;
        __nv_bfloat16 h, l; bf16split(v, h, l);
        g_Bh[(size_t)(r0 + r) * 512 + c0 + tx] = h;
        g_Bl[(size_t)(r0 + r) * 512 + c0 + tx] = l;
    }
    __syncthreads();
    for (int r = ty; r < 32; r += 8) {
        float v = t[tx][r];
        __nv_bfloat16 h, l; bf16split(v, h, l);
        g_BTh[(size_t)(c0 + r) * 512 + r0 + tx] = h;
        g_BTl[(size_t)(c0 + r) * 512 + r0 + tx] = l;
    }
}

// ---------------- init ----------------
__global__ void k_init() {
    int t = blockIdx.x * blockDim.x + threadIdx.x;
    if (t < MDIM) { g_cmax[t] = 0.0f; g_csum[t] = 0.0f; g_count[t] = 0; }
    if (t == 0) { g_comp = 0.0; g_sep = 0.0; }
}

// ---------------- L2 normalize + transpose to (N,C) + bf16 split + direct UQ output ----------------
__global__ void __launch_bounds__(256) k_normalize(const float* __restrict__ query,
                                                   float* __restrict__ out) {
    __shared__ float s[CDIM * 17];
    __shared__ float psum[256];
    __shared__ float rn[16];
    int p0 = blockIdx.x * 16;
    int b = p0 >> 12;
    int hw0 = p0 & 4095;
    const float* qb = query + (size_t)b * CDIM * HWDIM + hw0;
    int tid = threadIdx.x;
    #pragma unroll
    for (int it = 0; it < 32; it++) {
        int i = it * 256 + tid;
        int c = i >> 4, j = i & 15;
        s[c * 17 + j] = qb[(size_t)c * HWDIM + j];
    }
    __syncthreads();
    {
        int j = tid & 15, g = tid >> 4;
        float acc = 0.0f;
        #pragma unroll
        for (int cc = 0; cc < 32; cc++) {
            float v = s[(g * 32 + cc) * 17 + j];
            acc += v * v;
        }
        psum[tid] = acc;
    }
    __syncthreads();
    if (tid < 16) {
        float tot = 0.0f;
        #pragma unroll
        for (int g = 0; g < 16; g++) tot += psum[g * 16 + tid];
        rn[tid] = 1.0f / fmaxf(sqrtf(tot), 1e-12f);
    }
    __syncthreads();
    #pragma unroll
    for (int it = 0; it < 32; it++) {
        int i = it * 256 + tid;
        int c = i & 511, j = i >> 9;
        float v = s[c * 17 + j] * rn[j];
        size_t idx = (size_t)(p0 + j) * CDIM + c;
        __nv_bfloat16 h, l; bf16split(v, h, l);
        g_Ah[idx] = h;
        g_Al[idx] = l;
    }
    float* ob = out + (size_t)b * (1024LL * 4096LL) + hw0;
    #pragma unroll
    for (int it = 0; it < 32; it++) {
        int i = it * 256 + tid;
        int c = i >> 4, j = i & 15;
        ob[(size_t)c * 4096 + j] = s[c * 17 + j] * rn[j];
    }
}

// ---------------- per-row pass on E (vectorized): softmaxes, top2, w, losses + sm splits ----------------
__global__ void __launch_bounds__(256) k_row(float* __restrict__ out_sq,
                                             float* __restrict__ out_sm,
                                             const float* __restrict__ keys) {
    __shared__ float cinv[512];
    __shared__ double wcomp[8], wsep[8];
    for (int i = threadIdx.x; i < 512; i += 256)
        cinv[i] = 1.0f / g_csum[i];
    __syncthreads();
    int warp = threadIdx.x >> 5, lane = threadIdx.x & 31;
    size_t n = (size_t)blockIdx.x * 8 + warp;
    const float4* erow4 = (const float4*)(g_E + n * 512);
    float4 ev4[4];
    #pragma unroll
    for (int t = 0; t < 4; t++) ev4[t] = erow4[t * 32 + lane];

    // top2 on E (monotone in score); col index c = (t*32+lane)*4 + j
    float v1 = -FLT_MAX, v2 = -FLT_MAX; int i1 = 0, i2 = 0;
    #pragma unroll
    for (int t = 0; t < 4; t++) {
        const float* e = (const float*)&ev4[t];
        int cb = (t * 32 + lane) * 4;
        #pragma unroll
        for (int j = 0; j < 4; j++) {
            float v = e[j]; int c = cb + j;
            if (v > v1) { v2 = v1; i2 = i1; v1 = v; i1 = c; }
            else if (v > v2) { v2 = v; i2 = c; }
        }
    }
    #pragma unroll
    for (int off = 16; off; off >>= 1) {
        float ov1 = __shfl_down_sync(0xffffffffu, v1, off);
        int   oi1 = __shfl_down_sync(0xffffffffu, i1, off);
        float ov2 = __shfl_down_sync(0xffffffffu, v2, off);
        int   oi2 = __shfl_down_sync(0xffffffffu, i2, off);
        if (ov1 > v1) { v2 = v1; i2 = i1; v1 = ov1; i1 = oi1; if (ov2 > v2) { v2 = ov2; i2 = oi2; } }
        else if (ov1 > v2) { v2 = ov1; i2 = oi1; }
    }
    v1 = __shfl_sync(0xffffffffu, v1, 0);
    i1 = __shfl_sync(0xffffffffu, i1, 0);
    i2 = __shfl_sync(0xffffffffu, i2, 0);

    // row sum of E
    float rs = 0.0f;
    #pragma unroll
    for (int t = 0; t < 4; t++) rs += ev4[t].x + ev4[t].y + ev4[t].z + ev4[t].w;
    #pragma unroll
    for (int o = 16; o; o >>= 1) rs += __shfl_xor_sync(0xffffffffu, rs, o);
    float inv_rs = 1.0f / rs;

    float4* smrow4 = (float4*)(out_sm + n * 512);
    float4* sqrow4 = (float4*)(out_sq + n * 512);
    #pragma unroll
    for (int t = 0; t < 4; t++) {
        int f4i = t * 32 + lane;
        int cb = f4i * 4;
        const float* e = (const float*)&ev4[t];
        float4 sv = make_float4(e[0] * inv_rs, e[1] * inv_rs, e[2] * inv_rs, e[3] * inv_rs);
        smrow4[f4i] = sv;
        sqrow4[f4i] = make_float4(e[0] * cinv[cb], e[1] * cinv[cb + 1],
                                  e[2] * cinv[cb + 2], e[3] * cinv[cb + 3]);
        __nv_bfloat16 h0, l0, h1, l1, h2, l2, h3, l3;
        bf16split(sv.x, h0, l0); bf16split(sv.y, h1, l1);
        bf16split(sv.z, h2, l2); bf16split(sv.w, h3, l3);
        *(uint2*)&g_Sh[n * 512 + cb] = make_uint2(packbf(h0, h1), packbf(h2, h3));
        *(uint2*)&g_Sl[n * 512 + cb] = make_uint2(packbf(l0, l1), packbf(l2, l3));
    }
    if (lane == 0) {
        g_gi[n] = i1;
        g_w[n] = v1 / g_cmax[i1];
        atomicAdd(&g_count[i1], 1);
    }

    const uint2* qh2 = (const uint2*)(g_Ah + n * 512);
    const uint2* ql2 = (const uint2*)(g_Al + n * 512);
    const float4* pk4 = (const float4*)(keys + (size_t)i1 * 512);
    const float4* nk4 = (const float4*)(keys + (size_t)i2 * 512);
    float comp = 0.0f, dp = 0.0f, dn = 0.0f;
    #pragma unroll
    for (int t = 0; t < 4; t++) {
        int f4i = t * 32 + lane;
        uint2 qhv = qh2[f4i], qlv = ql2[f4i];
        float4 pv = pk4[f4i], nv = nk4[f4i];
        float q[4], p[4], gg[4];
        __nv_bfloat162 hq0 = *(__nv_bfloat162*)&qhv.x, hq1 = *(__nv_bfloat162*)&qhv.y;
        __nv_bfloat162 lq0 = *(__nv_bfloat162*)&qlv.x, lq1 = *(__nv_bfloat162*)&qlv.y;
        q[0] = __bfloat162float(hq0.x) + __bfloat162float(lq0.x);
        q[1] = __bfloat162float(hq0.y) + __bfloat162float(lq0.y);
        q[2] = __bfloat162float(hq1.x) + __bfloat162float(lq1.x);
        q[3] = __bfloat162float(hq1.y) + __bfloat162float(lq1.y);
        p[0] = pv.x; p[1] = pv.y; p[2] = pv.z; p[3] = pv.w;
        gg[0] = nv.x; gg[1] = nv.y; gg[2] = nv.z; gg[3] = nv.w;
        #pragma unroll
        for (int j = 0; j < 4; j++) {
            float d0 = q[j] - p[j]; comp += d0 * d0;
            float d1 = d0 + 1e-6f; dp += d1 * d1;
            float d2 = (q[j] - gg[j]) + 1e-6f; dn += d2 * d2;
        }
    }
    #pragma unroll
    for (int o = 16; o; o >>= 1) {
        comp += __shfl_xor_sync(0xffffffffu, comp, o);
        dp   += __shfl_xor_sync(0xffffffffu, dp, o);
        dn   += __shfl_xor_sync(0xffffffffu, dn, o);
    }
    if (lane == 0) {
        wcomp[warp] = (double)comp;
        wsep[warp] = (double)fmaxf(0.0f, sqrtf(dp) - sqrtf(dn) + 1.0f);
    }
    __syncthreads();
    if (threadIdx.x == 0) {
        double c = 0.0, s = 0.0;
        for (int wv = 0; wv < 8; wv++) { c += wcomp[wv]; s += wsep[wv]; }
        atomicAdd(&g_comp, c);
        atomicAdd(&g_sep, s);
    }
}

// ---------------- counting sort of rows by gi ----------------
__global__ void __launch_bounds__(512) k_scan() {
    __shared__ int s[512];
    int t = threadIdx.x;
    int v = g_count[t];
    s[t] = v;
    __syncthreads();
    for (int off = 1; off < 512; off <<= 1) {
        int add = (t >= off) ? s[t - off] : 0;
        __syncthreads();
        s[t] += add;
        __syncthreads();
    }
    g_offset[t + 1] = s[t];
    if (t == 0) g_offset[0] = 0;
    g_cursor[t] = s[t] - v;
}

__global__ void k_scatter() {
    for (int n = blockIdx.x * blockDim.x + threadIdx.x; n < NTOT; n += gridDim.x * blockDim.x) {
        int m = g_gi[n];
        int idx = atomicAdd(&g_cursor[m], 1);
        g_list[idx] = n;
    }
}

// ---------------- memory update: segment sum + l2norm ----------------
__global__ void __launch_bounds__(512) k_update(const float* __restrict__ keys,
                                                float* __restrict__ outUM) {
    int m = blockIdx.x;
    int t = threadIdx.x;
    __shared__ int sln[256];
    __shared__ float slw[256];
    __shared__ float red[16];
    __shared__ float rn_s;
    int beg = g_offset[m], end = g_offset[m + 1];
    float acc = 0.0f;
    for (int base = beg; base < end; base += 256) {
        int cnt = min(256, end - base);
        __syncthreads();
        if (t < cnt) { int n = g_list[base + t]; sln[t] = n; slw[t] = g_w[n]; }
        __syncthreads();
        for (int i = 0; i < cnt; i++) {
            size_t idx = (size_t)sln[i] * 512 + t;
            float q = __bfloat162float(g_Ah[idx]) + __bfloat162float(g_Al[idx]);
            acc += slw[i] * q;
        }
    }
    float um = acc + keys[(size_t)m * 512 + t];
    float ss = um * um;
    #pragma unroll
    for (int o = 16; o; o >>= 1) ss += __shfl_xor_sync(0xffffffffu, ss, o);
    if ((t & 31) == 0) red[t >> 5] = ss;
    __syncthreads();
    if (t == 0) {
        float x = 0.0f;
        for (int i = 0; i < 16; i++) x += red[i];
        rn_s = 1.0f / fmaxf(sqrtf(x), 1e-12f);
    }
    __syncthreads();
    outUM[(size_t)m * 512 + t] = um * rn_s;
}

// ---------------- losses ----------------
__global__ void k_finalize(float* __restrict__ out) {
    out[OFF_SEP] = (float)(g_sep / (double)NTOT);
    out[OFF_COMP] = (float)(g_comp / ((double)NTOT * (double)CDIM));
}

// ---------------- launch ----------------
extern "C" void kernel_launch(void* const* d_in, const int* in_sizes, int n_in,
                              void* d_out, int out_size) {
    const float* query = (const float*)d_in[0];
    const float* keys  = (const float*)d_in[1];
    float* out = (float*)d_out;

    float* p_E = nullptr;
    __nv_bfloat16 *p_Ah = nullptr, *p_Al = nullptr, *p_Sh = nullptr, *p_Sl = nullptr;
    __nv_bfloat16 *p_Bh = nullptr, *p_Bl = nullptr, *p_BTh = nullptr, *p_BTl = nullptr;
    cudaGetSymbolAddress((void**)&p_E, g_E);
    cudaGetSymbolAddress((void**)&p_Ah, g_Ah);
    cudaGetSymbolAddress((void**)&p_Al, g_Al);
    cudaGetSymbolAddress((void**)&p_Sh, g_Sh);
    cudaGetSymbolAddress((void**)&p_Sl, g_Sl);
    cudaGetSymbolAddress((void**)&p_Bh, g_Bh);
    cudaGetSymbolAddress((void**)&p_Bl, g_Bl);
    cudaGetSymbolAddress((void**)&p_BTh, g_BTh);
    cudaGetSymbolAddress((void**)&p_BTl, g_BTl);

    cudaFuncSetAttribute(k_mma<0>, cudaFuncAttributeMaxDynamicSharedMemorySize, 49152);
    cudaFuncSetAttribute(k_mma<1>, cudaFuncAttributeMaxDynamicSharedMemorySize, 49152);

    k_init<<<2, 256>>>();
    k_normalize<<<NTOT / 16, 256>>>(query, out);
    k_prepkeys<<<dim3(16, 16), dim3(32, 8)>>>(keys);
    k_mma<0><<<dim3(4, NTOT / 64), 256, 49152>>>(p_Ah, p_Al, p_Bh, p_Bl, p_E);
    k_row<<<NTOT / 8, 256>>>(out + OFF_SQ, out + OFF_SM, keys);
    k_scan<<<1, 512>>>();
    k_scatter<<<64, 256>>>();
    k_update<<<MDIM, 512>>>(keys, out + OFF_UM);
    k_mma<1><<<dim3(4, NTOT / 64), 256, 49152>>>(p_Sh, p_Sl, p_BTh, p_BTl, out);
    k_finalize<<<1, 1>>>(out);
}